// round 12
// baseline (speedup 1.0000x reference)
#include <cuda_runtime.h>
#include <math.h>

#define B_ 2
#define C_ 10
#define N_ 100
#define M_ 50
#define HW 9216      // 96*96
#define HPWP 576     // 24*24
#define KSPLIT 72
#define KCHUNK 128   // 9216/72
#define KK 32
#define STR 34
#define NLOC 50                        // n per dots block (n-split)
#define T_FLOATS (M_ * STR)            // 1700
#define PGL_FLOATS (NLOC * STR)        // 1700
#define BUF_FLOATS (T_FLOATS + 2 * PGL_FLOATS)  // 5100
#define DSMEM_BYTES (2 * BUF_FLOATS * 4)        // 40800
#define NQ 8
#define TWO_PI_F 6.2831854820251465f
#define PI_F 3.1415927410125732f

typedef unsigned long long ull;

// ---------------- scratch ----------------
__device__ __align__(16) float g_P[B_ * N_ * HW];
__device__ __align__(16) float g_G[B_ * N_ * HW];
__device__ __align__(16) float g_Sp[B_ * N_];
__device__ __align__(16) float g_F0c[B_ * N_ * NQ];
__device__ __align__(16) float g_stPart[B_ * M_ * KSPLIT];
// layout: [b][n][m][ks]
__device__ __align__(16) float g_part1[B_ * N_ * M_ * KSPLIT];
__device__ __align__(16) float g_part2[B_ * N_ * M_ * KSPLIT];

__constant__ float c_w[4] = {0.625f, 0.875f, 0.125f, 0.375f};

#define FMA2(d, a, b, c) \
    asm("fma.rn.f32x2 %0, %1, %2, %3;" : "=l"(d) : "l"(a), "l"(b), "l"(c))

// paired reduce over 288 threads (9 warps); valid in thread 0
__device__ __forceinline__ float2 blockReduceSum2_288(float a, float b, float2* sh) {
    int lane = threadIdx.x & 31;
    int wid = threadIdx.x >> 5;
    #pragma unroll
    for (int o = 16; o > 0; o >>= 1) {
        a += __shfl_down_sync(0xffffffffu, a, o);
        b += __shfl_down_sync(0xffffffffu, b, o);
    }
    if (lane == 0) sh[wid] = make_float2(a, b);
    __syncthreads();
    float2 v = (threadIdx.x < 9) ? sh[threadIdx.x] : make_float2(0.f, 0.f);
    if (wid == 0) {
        #pragma unroll
        for (int o = 8; o > 0; o >>= 1) {
            v.x += __shfl_down_sync(0xffffffffu, v.x, o);
            v.y += __shfl_down_sync(0xffffffffu, v.y, o);
        }
    }
    return v;
}

// ------ kernel 1: convert-only resize; 288 threads, 1 group/thread ------
__global__ void __launch_bounds__(288) k_pre(const float* __restrict__ pred_mask) {
    __shared__ float sm[HPWP];
    __shared__ float2 red2[9];
    int tid = threadIdx.x;
    int bc = blockIdx.x;          // 0..1599
    int bn = bc >> 3;
    int q  = bc & 7;

    float2 v2 = ((const float2*)(pred_mask + (size_t)bn * HPWP))[tid];
    *(float2*)(sm + (tid << 1)) = v2;
    float ssum = (q == 0) ? (v2.x + v2.y) : 0.0f;
    __syncthreads();

    float* Pout = g_P + (size_t)bn * HW + q * (12 * 96);
    float* Gout = g_G + (size_t)bn * HW + q * (12 * 96);

    // one 4-px group per thread: 12 rows x 24 x-groups = 288
    int r = tid / 24;
    int j = tid - r * 24;
    int yg = q * 12 + r;
    int iy = (yg - 2) >> 2;
    float wy = c_w[yg & 3];
    int iy0 = max(iy, 0) * 24, iy1 = min(iy + 1, 23) * 24;
    int cm = max(j - 1, 0), cp = min(j + 1, 23);

    float a0 = sm[iy0 + cm], a1 = sm[iy0 + j], a2 = sm[iy0 + cp];
    float b0 = sm[iy1 + cm], b1 = sm[iy1 + j], b2 = sm[iy1 + cp];

    float t0 = a0 + 0.625f * (a1 - a0);
    float t1 = a0 + 0.875f * (a1 - a0);
    float t2 = a1 + 0.125f * (a2 - a1);
    float t3 = a1 + 0.375f * (a2 - a1);
    float u0 = b0 + 0.625f * (b1 - b0);
    float u1 = b0 + 0.875f * (b1 - b0);
    float u2 = b1 + 0.125f * (b2 - b1);
    float u3 = b1 + 0.375f * (b2 - b1);

    float pv[4];
    pv[0] = t0 + wy * (u0 - t0);
    pv[1] = t1 + wy * (u1 - t1);
    pv[2] = t2 + wy * (u2 - t2);
    pv[3] = t3 + wy * (u3 - t3);

    float gv[4];
    float sf0 = 0.0f;
    #pragma unroll
    for (int k = 0; k < 4; k++) {
        float pc = fminf(fmaxf(pv[k], 0.001f), 0.999f);
        float omc = 1.0f - pc;
        float f1 = 0.25f * (-__logf(pc)) * omc * omc;
        float f0 = 0.75f * (-__logf(omc)) * pc * pc;
        gv[k] = f1 - f0;
        sf0 += f0;
    }
    int o = r * 96 + j * 4;
    *(float4*)(Pout + o) = make_float4(pv[0], pv[1], pv[2], pv[3]);
    *(float4*)(Gout + o) = make_float4(gv[0], gv[1], gv[2], gv[3]);

    float2 ts = blockReduceSum2_288(sf0, ssum, red2);
    if (tid == 0) {
        g_F0c[bn * NQ + q] = ts.x;
        if (q == 0) g_Sp[bn] = 16.0f * ts.y;
    }
}

// ------ kernel 2: dots, n-split (50n x 50m per block), 2 blocks/SM --------
__global__ void __launch_bounds__(256) k_dots(const float* __restrict__ tmask) {
    extern __shared__ __align__(16) float dsm[];
    int ks = blockIdx.x;
    int b  = blockIdx.y;
    int nh = blockIdx.z;   // n-half
    int tid = threadIdx.x;

    int mg = tid % 10;
    int ng = tid / 10;     // 0..24 active
    bool active = tid < 250;
    int m0 = mg * 5;
    int n0loc = ng * 2;

    const float* Tbase = tmask + (size_t)b * M_ * HW;
    const float* Pbase = g_P + (size_t)(b * N_ + nh * NLOC) * HW;
    const float* Gbase = g_G + (size_t)(b * N_ + nh * NLOC) * HW;

    ull a1[5][2], a2[5][2];
    #pragma unroll
    for (int i = 0; i < 5; i++)
        #pragma unroll
        for (int j = 0; j < 2; j++) { a1[i][j] = 0ULL; a2[i][j] = 0ULL; }

    // load mapping: 400 float4 per array per stage; e=tid (A) and e=tid+256 (B)
    int rowA = tid >> 3, cA = (tid & 7) << 2;
    int eB = tid + 256;
    int rowB = eB >> 3, cB = (eB & 7) << 2;
    bool hasB = tid < 144;

    float4 tAq, tBq, pAq, pBq, gAq, gBq;
    float stA = 0.0f, stB = 0.0f;
    int kbeg = ks * KCHUNK;

    // prefetch stage 0
    {
        int k0 = kbeg;
        tAq = *(const float4*)(Tbase + (size_t)rowA * HW + k0 + cA);
        stA += (fabsf(tAq.x) + fabsf(tAq.y)) + (fabsf(tAq.z) + fabsf(tAq.w));
        pAq = *(const float4*)(Pbase + (size_t)rowA * HW + k0 + cA);
        gAq = *(const float4*)(Gbase + (size_t)rowA * HW + k0 + cA);
        if (hasB) {
            tBq = *(const float4*)(Tbase + (size_t)rowB * HW + k0 + cB);
            stB += (fabsf(tBq.x) + fabsf(tBq.y)) + (fabsf(tBq.z) + fabsf(tBq.w));
            pBq = *(const float4*)(Pbase + (size_t)rowB * HW + k0 + cB);
            gBq = *(const float4*)(Gbase + (size_t)rowB * HW + k0 + cB);
        }
        float* bt = dsm;
        float* bp = bt + T_FLOATS;
        float* bg = bp + PGL_FLOATS;
        float* d;
        d = bt + rowA * STR + cA;
        *(float2*)(d) = make_float2(tAq.x, tAq.y);
        *(float2*)(d + 2) = make_float2(tAq.z, tAq.w);
        d = bp + rowA * STR + cA;
        *(float2*)(d) = make_float2(pAq.x, pAq.y);
        *(float2*)(d + 2) = make_float2(pAq.z, pAq.w);
        d = bg + rowA * STR + cA;
        *(float2*)(d) = make_float2(gAq.x, gAq.y);
        *(float2*)(d + 2) = make_float2(gAq.z, gAq.w);
        if (hasB) {
            d = bt + rowB * STR + cB;
            *(float2*)(d) = make_float2(tBq.x, tBq.y);
            *(float2*)(d + 2) = make_float2(tBq.z, tBq.w);
            d = bp + rowB * STR + cB;
            *(float2*)(d) = make_float2(pBq.x, pBq.y);
            *(float2*)(d + 2) = make_float2(pBq.z, pBq.w);
            d = bg + rowB * STR + cB;
            *(float2*)(d) = make_float2(gBq.x, gBq.y);
            *(float2*)(d + 2) = make_float2(gBq.z, gBq.w);
        }
    }
    __syncthreads();

    #pragma unroll
    for (int s = 0; s < KCHUNK / KK; s++) {
        int cur = s & 1;
        if (s < KCHUNK / KK - 1) {
            int k0 = kbeg + (s + 1) * KK;
            tAq = *(const float4*)(Tbase + (size_t)rowA * HW + k0 + cA);
            stA += (fabsf(tAq.x) + fabsf(tAq.y)) + (fabsf(tAq.z) + fabsf(tAq.w));
            pAq = *(const float4*)(Pbase + (size_t)rowA * HW + k0 + cA);
            gAq = *(const float4*)(Gbase + (size_t)rowA * HW + k0 + cA);
            if (hasB) {
                tBq = *(const float4*)(Tbase + (size_t)rowB * HW + k0 + cB);
                stB += (fabsf(tBq.x) + fabsf(tBq.y)) + (fabsf(tBq.z) + fabsf(tBq.w));
                pBq = *(const float4*)(Pbase + (size_t)rowB * HW + k0 + cB);
                gBq = *(const float4*)(Gbase + (size_t)rowB * HW + k0 + cB);
            }
        }

        {
            const float* bt = dsm + cur * BUF_FLOATS;
            const ull* sh_t2 = (const ull*)bt;
            const ull* sh_p2 = (const ull*)(bt + T_FLOATS);
            const ull* sh_g2 = (const ull*)(bt + T_FLOATS + PGL_FLOATS);
            if (active) {
                #pragma unroll
                for (int kp = 0; kp < KK / 2; kp++) {
                    ull tv[5], pv[2], gv[2];
                    #pragma unroll
                    for (int i = 0; i < 5; i++) tv[i] = sh_t2[(m0 + i) * (STR / 2) + kp];
                    #pragma unroll
                    for (int j = 0; j < 2; j++) {
                        pv[j] = sh_p2[(n0loc + j) * (STR / 2) + kp];
                        gv[j] = sh_g2[(n0loc + j) * (STR / 2) + kp];
                    }
                    #pragma unroll
                    for (int i = 0; i < 5; i++) {
                        #pragma unroll
                        for (int j = 0; j < 2; j++) {
                            FMA2(a1[i][j], tv[i], pv[j], a1[i][j]);
                            FMA2(a2[i][j], tv[i], gv[j], a2[i][j]);
                        }
                    }
                }
            }
        }

        if (s < KCHUNK / KK - 1) {
            float* bt = dsm + (cur ^ 1) * BUF_FLOATS;
            float* bp = bt + T_FLOATS;
            float* bg = bp + PGL_FLOATS;
            float* d;
            d = bt + rowA * STR + cA;
            *(float2*)(d) = make_float2(tAq.x, tAq.y);
            *(float2*)(d + 2) = make_float2(tAq.z, tAq.w);
            d = bp + rowA * STR + cA;
            *(float2*)(d) = make_float2(pAq.x, pAq.y);
            *(float2*)(d + 2) = make_float2(pAq.z, pAq.w);
            d = bg + rowA * STR + cA;
            *(float2*)(d) = make_float2(gAq.x, gAq.y);
            *(float2*)(d + 2) = make_float2(gAq.z, gAq.w);
            if (hasB) {
                d = bt + rowB * STR + cB;
                *(float2*)(d) = make_float2(tBq.x, tBq.y);
                *(float2*)(d + 2) = make_float2(tBq.z, tBq.w);
                d = bp + rowB * STR + cB;
                *(float2*)(d) = make_float2(pBq.x, pBq.y);
                *(float2*)(d + 2) = make_float2(pBq.z, pBq.w);
                d = bg + rowB * STR + cB;
                *(float2*)(d) = make_float2(gBq.x, gBq.y);
                *(float2*)(d + 2) = make_float2(gBq.z, gBq.w);
            }
        }
        __syncthreads();
    }

    if (active) {
        #pragma unroll
        for (int i = 0; i < 5; i++) {
            #pragma unroll
            for (int j = 0; j < 2; j++) {
                int n = nh * NLOC + n0loc + j;
                int m = m0 + i;
                size_t idx = ((size_t)(b * N_ + n) * M_ + m) * KSPLIT + ks;
                float2 v1 = *(float2*)&a1[i][j];
                float2 v2 = *(float2*)&a2[i][j];
                g_part1[idx] = v1.x + v1.y;
                g_part2[idx] = v2.x + v2.y;
            }
        }
    }

    // St partials (only nh==0 blocks; T read twice otherwise)
    if (nh == 0) {
        stA += __shfl_down_sync(0xffffffffu, stA, 4, 8);
        stA += __shfl_down_sync(0xffffffffu, stA, 2, 8);
        stA += __shfl_down_sync(0xffffffffu, stA, 1, 8);
        stB += __shfl_down_sync(0xffffffffu, stB, 4, 8);
        stB += __shfl_down_sync(0xffffffffu, stB, 2, 8);
        stB += __shfl_down_sync(0xffffffffu, stB, 1, 8);
        if ((tid & 7) == 0) {
            int mA = tid >> 3;   // 0..31
            g_stPart[((size_t)(b * M_ + mA)) * KSPLIT + ks] = stA;
            if (tid < 144) {
                int mB = 32 + (tid >> 3);  // 32..49
                g_stPart[((size_t)(b * M_ + mB)) * KSPLIT + ks] = stB;
            }
        }
    }
}

// ------ kernel 3: assemble (2 threads per output) ------
__global__ void k_assemble(const float* __restrict__ pred_prob,
                           const float* __restrict__ pred_mom,
                           const int*   __restrict__ tcls,
                           const float* __restrict__ tmom,
                           float* __restrict__ out) {
    int gid = blockIdx.x * blockDim.x + threadIdx.x;
    int oid = gid >> 1;
    int part = gid & 1;
    bool valid = oid < B_ * N_ * M_;
    int o = valid ? oid : 0;
    int m = o % M_;
    int n = (o / M_) % N_;
    int b = o / (N_ * M_);

    size_t base = (size_t)o * KSPLIT + part * (KSPLIT / 2);
    const float4* p1 = (const float4*)(g_part1 + base);
    const float4* p2 = (const float4*)(g_part2 + base);
    size_t sb = ((size_t)(b * M_ + m)) * KSPLIT + part * (KSPLIT / 2);
    const float4* ps = (const float4*)(g_stPart + sb);
    float dot1 = 0.f, dot2 = 0.f, sts = 0.f;
    #pragma unroll
    for (int i = 0; i < KSPLIT / 8; i++) {
        float4 v = p1[i];
        float4 w = p2[i];
        float4 y = ps[i];
        dot1 += (v.x + v.y) + (v.z + v.w);
        dot2 += (w.x + w.y) + (w.z + w.w);
        sts  += (y.x + y.y) + (y.z + y.w);
    }
    float f0s = 0.f;
    {
        const float4* pf = (const float4*)(g_F0c + (size_t)(b * N_ + n) * NQ + part * 4);
        float4 x = pf[0];
        f0s = (x.x + x.y) + (x.z + x.w);
    }
    dot1 += __shfl_down_sync(0xffffffffu, dot1, 1);
    dot2 += __shfl_down_sync(0xffffffffu, dot2, 1);
    f0s  += __shfl_down_sync(0xffffffffu, f0s, 1);
    sts  += __shfl_down_sync(0xffffffffu, sts, 1);

    if (!valid || part) return;

    int cls = tcls[b * M_ + m];
    if (cls <= 0) { out[oid] = 100000.0f; return; }

    float Sp = g_Sp[b * N_ + n];
    float pos = Sp + sts;
    float cost_dice = 1.0f - 2.0f * dot1 / (pos + 0.001f);
    float cost_focal = (f0s + dot2) * (1.0f / (float)HW);
    float cost_class = -pred_prob[((size_t)b * C_ + cls) * N_ + n];

    const float* pmv = pred_mom + (size_t)(b * N_ + n) * 4;
    float p0 = __expf(fminf(pmv[0], 10.0f));
    float p1f = TWO_PI_F / (1.0f + __expf(-pmv[1]));
    float p2f = TWO_PI_F / (1.0f + __expf(-pmv[2]));
    float p3 = __expf(fminf(pmv[3], 10.0f));
    const float* tmv = tmom + (size_t)(b * M_ + m) * 4;
    float t0 = tmv[0], t1 = tmv[1], t2 = tmv[2], t3 = tmv[3];

    float pe = (t2 - p2f > PI_F) ? TWO_PI_F : 0.0f;
    float te = (p2f - t2 > PI_F) ? TWO_PI_F : 0.0f;
    float l1 = (fabsf(p0 / (t0 + 0.001f) - 1.0f)
              + fabsf(p1f / (t1 + 0.001f) - 1.0f)
              + fabsf((p2f + pe) / (t2 + te + 0.001f) - 1.0f)
              + fabsf(p3 / (t3 + 0.001f) - 1.0f)) * 0.25f;

    float w1 = p0, x1 = p1f, y1 = p2f, h1 = p3;
    float w2 = t0, x2 = t1, y2 = t2, h2 = t3;
    float y1e = (y2 - y1 > PI_F) ? TWO_PI_F : 0.0f;
    float y2e = (y1 - y2 > PI_F) ? TWO_PI_F : 0.0f;
    y1 += y1e;
    y2 += y2e;
    float r1 = x1 + w1 * 0.5f, l1b = x1 - w1 * 0.5f;
    float r2 = x2 + w2 * 0.5f, l2b = x2 - w2 * 0.5f;
    float u1 = y1 + h1 * 0.5f, d1 = y1 - h1 * 0.5f;
    float u2 = y2 + h2 * 0.5f, d2 = y2 - h2 * 0.5f;
    float w = fminf(r1, r2) - fmaxf(l1b, l2b);
    float h = fminf(u1, u2) - fmaxf(d1, d2);
    float iou = (w > 0.0f && h > 0.0f)
                ? (w * h) / (w1 * h1 + w2 * h2 - w * h + 0.001f) : 0.0f;
    float cw = fmaxf(r1, r2) - fminf(l1b, l2b);
    float ch = fmaxf(u1, u2) - fminf(d1, d2);
    float cw2 = cw * cw, ch2 = ch * ch;
    float dw = w1 - w2, dh = h1 - h2;
    float rho_w = dw * dw / (cw2 + 0.001f);
    float rho_h = dh * dh / (ch2 + 0.001f);
    float dx = x1 - x2, dy = y1 - y2;
    float rho_d = (dx * dx + dy * dy) / (cw2 + ch2 + 0.001f);
    float ce = 1.0f - iou + rho_d + rho_w + rho_h;

    out[oid] = 0.25f * cost_focal + 0.75f * cost_dice + cost_class
             + 0.8f * l1 + 0.2f * ce;
}

extern "C" void kernel_launch(void* const* d_in, const int* in_sizes, int n_in,
                              void* d_out, int out_size) {
    const float* pred_prob = (const float*)d_in[0];
    const float* pred_mask = (const float*)d_in[1];
    const float* pred_mom  = (const float*)d_in[2];
    const int*   tcls      = (const int*)d_in[3];
    const float* tmask     = (const float*)d_in[4];
    const float* tmom      = (const float*)d_in[5];
    float* out = (float*)d_out;

    static int configured = 0;
    if (!configured) {
        cudaFuncSetAttribute(k_dots, cudaFuncAttributeMaxDynamicSharedMemorySize,
                             DSMEM_BYTES);
        configured = 1;
    }

    k_pre<<<B_ * N_ * NQ, 288>>>(pred_mask);
    dim3 grid(KSPLIT, B_, 2);
    k_dots<<<grid, 256, DSMEM_BYTES>>>(tmask);
    int total_threads = 2 * B_ * N_ * M_;
    k_assemble<<<(total_threads + 255) / 256, 256>>>(pred_prob, pred_mom, tcls, tmom, out);
}

// round 13
// speedup vs baseline: 1.0667x; 1.0667x over previous
#include <cuda_runtime.h>
#include <math.h>

#define B_ 2
#define C_ 10
#define N_ 100
#define M_ 50
#define HW 9216      // 96*96
#define HPWP 576     // 24*24
#define KSPLIT 72
#define KCHUNK 128   // 9216/72
#define KK 32
#define STR 34
#define T_FLOATS (M_ * STR)
#define PG_FLOATS (N_ * STR)
#define BUF_FLOATS (T_FLOATS + 2 * PG_FLOATS)  // 8500
#define DSMEM_BYTES (2 * BUF_FLOATS * 4)       // 68000
#define NQ 8
#define TWO_PI_F 6.2831854820251465f
#define PI_F 3.1415927410125732f

typedef unsigned long long ull;

// ---------------- scratch ----------------
__device__ __align__(16) float g_P[B_ * N_ * HW];
__device__ __align__(16) float g_G[B_ * N_ * HW];
__device__ __align__(16) float g_Sp[B_ * N_];
__device__ __align__(16) float g_F0c[B_ * N_ * NQ];
__device__ __align__(16) float g_St[B_ * M_];
// layout: [b][n][m][ks]
__device__ __align__(16) float g_part1[B_ * N_ * M_ * KSPLIT];
__device__ __align__(16) float g_part2[B_ * N_ * M_ * KSPLIT];

__constant__ float c_w[4] = {0.625f, 0.875f, 0.125f, 0.375f};

#define FMA2(d, a, b, c) \
    asm("fma.rn.f32x2 %0, %1, %2, %3;" : "=l"(d) : "l"(a), "l"(b), "l"(c))

// paired reduce over 288 threads (9 warps); valid in thread 0
__device__ __forceinline__ float2 blockReduceSum2_288(float a, float b, float2* sh) {
    int lane = threadIdx.x & 31;
    int wid = threadIdx.x >> 5;
    #pragma unroll
    for (int o = 16; o > 0; o >>= 1) {
        a += __shfl_down_sync(0xffffffffu, a, o);
        b += __shfl_down_sync(0xffffffffu, b, o);
    }
    if (lane == 0) sh[wid] = make_float2(a, b);
    __syncthreads();
    float2 v = (threadIdx.x < 9) ? sh[threadIdx.x] : make_float2(0.f, 0.f);
    if (wid == 0) {
        #pragma unroll
        for (int o = 8; o > 0; o >>= 1) {
            v.x += __shfl_down_sync(0xffffffffu, v.x, o);
            v.y += __shfl_down_sync(0xffffffffu, v.y, o);
        }
    }
    return v;
}

// ------ kernel 1: conv blocks 0..1599 (1 group/thread) + St blocks 1600..1699
__global__ void __launch_bounds__(288) k_pre(const float* __restrict__ pred_mask,
                                             const float* __restrict__ tmask) {
    __shared__ float sm[HPWP];
    __shared__ float2 red2[9];
    int tid = threadIdx.x;
    int bc = blockIdx.x;

    if (bc < 1600) {
        int bn = bc >> 3;
        int q  = bc & 7;

        float2 v2 = ((const float2*)(pred_mask + (size_t)bn * HPWP))[tid];
        *(float2*)(sm + (tid << 1)) = v2;
        float ssum = (q == 0) ? (v2.x + v2.y) : 0.0f;
        __syncthreads();

        float* Pout = g_P + (size_t)bn * HW + q * (12 * 96);
        float* Gout = g_G + (size_t)bn * HW + q * (12 * 96);

        int r = tid / 24;
        int j = tid - r * 24;
        int yg = q * 12 + r;
        int iy = (yg - 2) >> 2;
        float wy = c_w[yg & 3];
        int iy0 = max(iy, 0) * 24, iy1 = min(iy + 1, 23) * 24;
        int cm = max(j - 1, 0), cp = min(j + 1, 23);

        float a0 = sm[iy0 + cm], a1 = sm[iy0 + j], a2 = sm[iy0 + cp];
        float b0 = sm[iy1 + cm], b1 = sm[iy1 + j], b2 = sm[iy1 + cp];

        float t0 = a0 + 0.625f * (a1 - a0);
        float t1 = a0 + 0.875f * (a1 - a0);
        float t2 = a1 + 0.125f * (a2 - a1);
        float t3 = a1 + 0.375f * (a2 - a1);
        float u0 = b0 + 0.625f * (b1 - b0);
        float u1 = b0 + 0.875f * (b1 - b0);
        float u2 = b1 + 0.125f * (b2 - b1);
        float u3 = b1 + 0.375f * (b2 - b1);

        float pv[4];
        pv[0] = t0 + wy * (u0 - t0);
        pv[1] = t1 + wy * (u1 - t1);
        pv[2] = t2 + wy * (u2 - t2);
        pv[3] = t3 + wy * (u3 - t3);

        float gv[4];
        float sf0 = 0.0f;
        #pragma unroll
        for (int k = 0; k < 4; k++) {
            float pc = fminf(fmaxf(pv[k], 0.001f), 0.999f);
            float omc = 1.0f - pc;
            float f1 = 0.25f * (-__logf(pc)) * omc * omc;
            float f0 = 0.75f * (-__logf(omc)) * pc * pc;
            gv[k] = f1 - f0;
            sf0 += f0;
        }
        int o = r * 96 + j * 4;
        *(float4*)(Pout + o) = make_float4(pv[0], pv[1], pv[2], pv[3]);
        *(float4*)(Gout + o) = make_float4(gv[0], gv[1], gv[2], gv[3]);

        float2 ts = blockReduceSum2_288(sf0, ssum, red2);
        if (tid == 0) {
            g_F0c[bn * NQ + q] = ts.x;
            if (q == 0) g_Sp[bn] = 16.0f * ts.y;
        }
    } else {
        int bm = bc - 1600;   // 0..99
        const float4* src = (const float4*)(tmask + (size_t)bm * HW);
        float s = 0.0f;
        for (int i = tid; i < HW / 4; i += 288) {
            float4 v = src[i];
            s += (fabsf(v.x) + fabsf(v.y)) + (fabsf(v.z) + fabsf(v.w));
        }
        float2 ts = blockReduceSum2_288(s, 0.0f, red2);
        if (tid == 0) g_St[bm] = ts.x;
    }
}

// ------ kernel 2: dots (R7 verbatim: 512 thr, full N, double-buffered) ----
__global__ void __launch_bounds__(512) k_dots(const float* __restrict__ tmask) {
    extern __shared__ __align__(16) float dsm[];
    int ks = blockIdx.x;
    int b  = blockIdx.y;
    int tid = threadIdx.x;

    int mg = tid % 10;
    int ng = tid / 10;
    bool active = tid < 500;
    int m0 = mg * 5;
    int n0 = ng * 2;

    const float* Tbase = tmask + (size_t)b * M_ * HW;
    const float* Pbase = g_P + (size_t)b * N_ * HW;
    const float* Gbase = g_G + (size_t)b * N_ * HW;

    ull a1[5][2], a2[5][2];
    #pragma unroll
    for (int i = 0; i < 5; i++)
        #pragma unroll
        for (int j = 0; j < 2; j++) { a1[i][j] = 0ULL; a2[i][j] = 0ULL; }

    int row0 = tid >> 3, c40 = (tid & 7) << 2;
    int e1 = tid + 512;
    int row1 = e1 >> 3, c41 = (e1 & 7) << 2;

    float4 ft, fp0, fg0, fp1, fg1;
    int kbeg = ks * KCHUNK;

    // prefetch stage 0
    {
        int k0 = kbeg;
        if (tid < 400) ft = *(const float4*)(Tbase + (size_t)row0 * HW + k0 + c40);
        fp0 = *(const float4*)(Pbase + (size_t)row0 * HW + k0 + c40);
        fg0 = *(const float4*)(Gbase + (size_t)row0 * HW + k0 + c40);
        if (tid < 288) {
            fp1 = *(const float4*)(Pbase + (size_t)row1 * HW + k0 + c41);
            fg1 = *(const float4*)(Gbase + (size_t)row1 * HW + k0 + c41);
        }
        float* bt = dsm;
        float* bp = bt + T_FLOATS;
        float* bg = bp + PG_FLOATS;
        if (tid < 400) {
            float* d = bt + row0 * STR + c40;
            *(float2*)(d) = make_float2(ft.x, ft.y);
            *(float2*)(d + 2) = make_float2(ft.z, ft.w);
        }
        {
            float* d = bp + row0 * STR + c40;
            *(float2*)(d) = make_float2(fp0.x, fp0.y);
            *(float2*)(d + 2) = make_float2(fp0.z, fp0.w);
            float* d2 = bg + row0 * STR + c40;
            *(float2*)(d2) = make_float2(fg0.x, fg0.y);
            *(float2*)(d2 + 2) = make_float2(fg0.z, fg0.w);
        }
        if (tid < 288) {
            float* d = bp + row1 * STR + c41;
            *(float2*)(d) = make_float2(fp1.x, fp1.y);
            *(float2*)(d + 2) = make_float2(fp1.z, fp1.w);
            float* d2 = bg + row1 * STR + c41;
            *(float2*)(d2) = make_float2(fg1.x, fg1.y);
            *(float2*)(d2 + 2) = make_float2(fg1.z, fg1.w);
        }
    }
    __syncthreads();

    #pragma unroll
    for (int s = 0; s < KCHUNK / KK; s++) {
        int cur = s & 1;
        if (s < KCHUNK / KK - 1) {
            int k0 = kbeg + (s + 1) * KK;
            if (tid < 400) ft = *(const float4*)(Tbase + (size_t)row0 * HW + k0 + c40);
            fp0 = *(const float4*)(Pbase + (size_t)row0 * HW + k0 + c40);
            fg0 = *(const float4*)(Gbase + (size_t)row0 * HW + k0 + c40);
            if (tid < 288) {
                fp1 = *(const float4*)(Pbase + (size_t)row1 * HW + k0 + c41);
                fg1 = *(const float4*)(Gbase + (size_t)row1 * HW + k0 + c41);
            }
        }

        {
            const float* bt = dsm + cur * BUF_FLOATS;
            const ull* sh_t2 = (const ull*)bt;
            const ull* sh_p2 = (const ull*)(bt + T_FLOATS);
            const ull* sh_g2 = (const ull*)(bt + T_FLOATS + PG_FLOATS);
            if (active) {
                #pragma unroll
                for (int kp = 0; kp < KK / 2; kp++) {
                    ull tv[5], pv[2], gv[2];
                    #pragma unroll
                    for (int i = 0; i < 5; i++) tv[i] = sh_t2[(m0 + i) * (STR / 2) + kp];
                    #pragma unroll
                    for (int j = 0; j < 2; j++) {
                        pv[j] = sh_p2[(n0 + j) * (STR / 2) + kp];
                        gv[j] = sh_g2[(n0 + j) * (STR / 2) + kp];
                    }
                    #pragma unroll
                    for (int i = 0; i < 5; i++) {
                        #pragma unroll
                        for (int j = 0; j < 2; j++) {
                            FMA2(a1[i][j], tv[i], pv[j], a1[i][j]);
                            FMA2(a2[i][j], tv[i], gv[j], a2[i][j]);
                        }
                    }
                }
            }
        }

        if (s < KCHUNK / KK - 1) {
            float* bt = dsm + (cur ^ 1) * BUF_FLOATS;
            float* bp = bt + T_FLOATS;
            float* bg = bp + PG_FLOATS;
            if (tid < 400) {
                float* d = bt + row0 * STR + c40;
                *(float2*)(d) = make_float2(ft.x, ft.y);
                *(float2*)(d + 2) = make_float2(ft.z, ft.w);
            }
            {
                float* d = bp + row0 * STR + c40;
                *(float2*)(d) = make_float2(fp0.x, fp0.y);
                *(float2*)(d + 2) = make_float2(fp0.z, fp0.w);
                float* d2 = bg + row0 * STR + c40;
                *(float2*)(d2) = make_float2(fg0.x, fg0.y);
                *(float2*)(d2 + 2) = make_float2(fg0.z, fg0.w);
            }
            if (tid < 288) {
                float* d = bp + row1 * STR + c41;
                *(float2*)(d) = make_float2(fp1.x, fp1.y);
                *(float2*)(d + 2) = make_float2(fp1.z, fp1.w);
                float* d2 = bg + row1 * STR + c41;
                *(float2*)(d2) = make_float2(fg1.x, fg1.y);
                *(float2*)(d2 + 2) = make_float2(fg1.z, fg1.w);
            }
        }
        __syncthreads();
    }

    if (active) {
        #pragma unroll
        for (int i = 0; i < 5; i++) {
            #pragma unroll
            for (int j = 0; j < 2; j++) {
                int n = n0 + j;
                int m = m0 + i;
                size_t idx = ((size_t)(b * N_ + n) * M_ + m) * KSPLIT + ks;
                float2 v1 = *(float2*)&a1[i][j];
                float2 v2 = *(float2*)&a2[i][j];
                g_part1[idx] = v1.x + v1.y;
                g_part2[idx] = v2.x + v2.y;
            }
        }
    }
}

// ------ kernel 3: assemble (2 threads per output) ------
__global__ void k_assemble(const float* __restrict__ pred_prob,
                           const float* __restrict__ pred_mom,
                           const int*   __restrict__ tcls,
                           const float* __restrict__ tmom,
                           float* __restrict__ out) {
    int gid = blockIdx.x * blockDim.x + threadIdx.x;
    int oid = gid >> 1;
    int part = gid & 1;
    bool valid = oid < B_ * N_ * M_;
    int o = valid ? oid : 0;
    int m = o % M_;
    int n = (o / M_) % N_;
    int b = o / (N_ * M_);

    size_t base = (size_t)o * KSPLIT + part * (KSPLIT / 2);
    const float4* p1 = (const float4*)(g_part1 + base);
    const float4* p2 = (const float4*)(g_part2 + base);
    float dot1 = 0.f, dot2 = 0.f;
    #pragma unroll
    for (int i = 0; i < KSPLIT / 8; i++) {
        float4 v = p1[i];
        float4 w = p2[i];
        dot1 += (v.x + v.y) + (v.z + v.w);
        dot2 += (w.x + w.y) + (w.z + w.w);
    }
    float f0s = 0.f;
    {
        const float4* pf = (const float4*)(g_F0c + (size_t)(b * N_ + n) * NQ + part * 4);
        float4 x = pf[0];
        f0s = (x.x + x.y) + (x.z + x.w);
    }
    dot1 += __shfl_down_sync(0xffffffffu, dot1, 1);
    dot2 += __shfl_down_sync(0xffffffffu, dot2, 1);
    f0s  += __shfl_down_sync(0xffffffffu, f0s, 1);

    if (!valid || part) return;

    int cls = tcls[b * M_ + m];
    if (cls <= 0) { out[oid] = 100000.0f; return; }

    float Sp = g_Sp[b * N_ + n];
    float St = g_St[b * M_ + m];
    float pos = Sp + St;
    float cost_dice = 1.0f - 2.0f * dot1 / (pos + 0.001f);
    float cost_focal = (f0s + dot2) * (1.0f / (float)HW);
    float cost_class = -pred_prob[((size_t)b * C_ + cls) * N_ + n];

    const float* pmv = pred_mom + (size_t)(b * N_ + n) * 4;
    float p0 = __expf(fminf(pmv[0], 10.0f));
    float p1f = TWO_PI_F / (1.0f + __expf(-pmv[1]));
    float p2f = TWO_PI_F / (1.0f + __expf(-pmv[2]));
    float p3 = __expf(fminf(pmv[3], 10.0f));
    const float* tmv = tmom + (size_t)(b * M_ + m) * 4;
    float t0 = tmv[0], t1 = tmv[1], t2 = tmv[2], t3 = tmv[3];

    float pe = (t2 - p2f > PI_F) ? TWO_PI_F : 0.0f;
    float te = (p2f - t2 > PI_F) ? TWO_PI_F : 0.0f;
    float l1 = (fabsf(p0 / (t0 + 0.001f) - 1.0f)
              + fabsf(p1f / (t1 + 0.001f) - 1.0f)
              + fabsf((p2f + pe) / (t2 + te + 0.001f) - 1.0f)
              + fabsf(p3 / (t3 + 0.001f) - 1.0f)) * 0.25f;

    float w1 = p0, x1 = p1f, y1 = p2f, h1 = p3;
    float w2 = t0, x2 = t1, y2 = t2, h2 = t3;
    float y1e = (y2 - y1 > PI_F) ? TWO_PI_F : 0.0f;
    float y2e = (y1 - y2 > PI_F) ? TWO_PI_F : 0.0f;
    y1 += y1e;
    y2 += y2e;
    float r1 = x1 + w1 * 0.5f, l1b = x1 - w1 * 0.5f;
    float r2 = x2 + w2 * 0.5f, l2b = x2 - w2 * 0.5f;
    float u1 = y1 + h1 * 0.5f, d1 = y1 - h1 * 0.5f;
    float u2 = y2 + h2 * 0.5f, d2 = y2 - h2 * 0.5f;
    float w = fminf(r1, r2) - fmaxf(l1b, l2b);
    float h = fminf(u1, u2) - fmaxf(d1, d2);
    float iou = (w > 0.0f && h > 0.0f)
                ? (w * h) / (w1 * h1 + w2 * h2 - w * h + 0.001f) : 0.0f;
    float cw = fmaxf(r1, r2) - fminf(l1b, l2b);
    float ch = fmaxf(u1, u2) - fminf(d1, d2);
    float cw2 = cw * cw, ch2 = ch * ch;
    float dw = w1 - w2, dh = h1 - h2;
    float rho_w = dw * dw / (cw2 + 0.001f);
    float rho_h = dh * dh / (ch2 + 0.001f);
    float dx = x1 - x2, dy = y1 - y2;
    float rho_d = (dx * dx + dy * dy) / (cw2 + ch2 + 0.001f);
    float ce = 1.0f - iou + rho_d + rho_w + rho_h;

    out[oid] = 0.25f * cost_focal + 0.75f * cost_dice + cost_class
             + 0.8f * l1 + 0.2f * ce;
}

extern "C" void kernel_launch(void* const* d_in, const int* in_sizes, int n_in,
                              void* d_out, int out_size) {
    const float* pred_prob = (const float*)d_in[0];
    const float* pred_mask = (const float*)d_in[1];
    const float* pred_mom  = (const float*)d_in[2];
    const int*   tcls      = (const int*)d_in[3];
    const float* tmask     = (const float*)d_in[4];
    const float* tmom      = (const float*)d_in[5];
    float* out = (float*)d_out;

    static int configured = 0;
    if (!configured) {
        cudaFuncSetAttribute(k_dots, cudaFuncAttributeMaxDynamicSharedMemorySize,
                             DSMEM_BYTES);
        configured = 1;
    }

    k_pre<<<1700, 288>>>(pred_mask, tmask);
    dim3 grid(KSPLIT, B_);
    k_dots<<<grid, 512, DSMEM_BYTES>>>(tmask);
    int total_threads = 2 * B_ * N_ * M_;
    k_assemble<<<(total_threads + 255) / 256, 256>>>(pred_prob, pred_mom, tcls, tmom, out);
}